// round 10
// baseline (speedup 1.0000x reference)
#include <cuda_runtime.h>
#include <cuda_bf16.h>
#include <math_constants.h>
#include <cstdint>

// Problem constants
#define NB   16
#define NC   1024
#define NT   16
#define NP   360          // H*W = 12*30
#define NK   120          // top-k
#define ROWS 482          // 1 + 120 + 1 + 360
#define CSPLIT 64
#define CCH  16                      // c per score block (NC/CSPLIT)
#define TSTRIDE ((size_t)NT * NP)    // 5760 floats between consecutive c
#define SROW 724                     // smem floats per c row (720 data + pad)

// Kernel-A block roles (bid order: producers before consumers -> no deadlock)
#define N_SCORE 1024                 // 16 b x 64 cs
#define BID_SORT N_SCORE
#define GRID_A  (N_SCORE + NB)

// Scratch (no device allocation allowed -> __device__ globals)
__device__ __align__(16) float g_spart[NB][CSPLIT][NP];   // 1.5 MB
__device__ __align__(16) float g_xt0[NB][NP][NC];         // 23.6 MB, f0 transposed
__device__ int g_topk[NB][128];
__device__ int g_cnt[NB * 32];   // per-b score-block counters (128B padded), init 0

// ---------------------------------------------------------------------------
// Kernel A: single pass over x.
//  score blocks (b, cs): cp.async the 16c x 720 (t0|t1) slab (45 KB) to smem;
//    - partial dot products from t0 half -> g_spart
//    - t1 half transposed -> out rows 122..481 (final data, no revisit)
//    - t0 half transposed -> g_xt0 (dense row-major per p, for the gather)
//  sort blocks (dispatched last): acquire-spin per-b counter, reduce partials,
//    bitonic 512 (desc score, asc idx tiebreak = lax.top_k), emit topk + cls.
// ---------------------------------------------------------------------------
__global__ void __launch_bounds__(256) k_phase1(const float* __restrict__ x,
                                                const float* __restrict__ cls,
                                                float* __restrict__ out)
{
    __shared__ __align__(16) float sbuf[CCH * SROW + 32];  // 46.5 KB, role-aliased
    const int bid = blockIdx.x;
    const int tid = threadIdx.x;

    if (bid < N_SCORE) {
        // ================= score + transpose path ==========================
        const int b  = bid >> 6;          // 0..15
        const int cs = bid & 63;          // 0..63

        float* xs    = sbuf;              // [CCH][SROW] (720 data floats used)
        float* cls_s = sbuf + CCH * SROW; // [CCH]

        const float* xbase = x + ((size_t)b * NC + (size_t)cs * CCH) * TSTRIDE;
        const unsigned int s_dst = (unsigned int)__cvta_generic_to_shared(xs);

        // 2880 16-byte async copies: 16 c-rows x 180 quads (t0+t1 contiguous)
        for (int q = tid; q < CCH * 180; q += 256) {
            const int c   = q / 180;
            const int off = q - c * 180;
            const float* src = xbase + (size_t)c * TSTRIDE + off * 4;
            asm volatile("cp.async.cg.shared.global [%0], [%1], 16;\n"
                         :: "r"(s_dst + (unsigned)(c * SROW + off * 4) * 4u), "l"(src));
        }
        if (tid < CCH)
            cls_s[tid] = cls[b * (NT * NC) + cs * CCH + tid];   // t=0 cls

        asm volatile("cp.async.commit_group;\ncp.async.wait_group 0;\n" ::: "memory");
        __syncthreads();

        // ---- partial dots from t0 half (90 p-quads) ----
        if (tid < NP / 4) {
            float4 acc = make_float4(0.f, 0.f, 0.f, 0.f);
            #pragma unroll
            for (int c = 0; c < CCH; ++c) {
                const float4 v = *reinterpret_cast<const float4*>(&xs[c * SROW + tid * 4]);
                const float  w = cls_s[c];
                acc.x = fmaf(w, v.x, acc.x);
                acc.y = fmaf(w, v.y, acc.y);
                acc.z = fmaf(w, v.z, acc.z);
                acc.w = fmaf(w, v.w, acc.w);
            }
            *reinterpret_cast<float4*>(&g_spart[b][cs][tid * 4]) = acc;
        }

        // ---- transposed writes: 360 p x 4 c-quads each for t0 and t1 ----
        const size_t obase = (size_t)b * ROWS * NC;
        const int    ccol  = cs * CCH;
        for (int idx = tid; idx < NP * 4; idx += 256) {
            const int p = idx >> 2;
            const int q = idx & 3;
            float4 v0, v1;
            v0.x = xs[(4 * q + 0) * SROW + p];
            v0.y = xs[(4 * q + 1) * SROW + p];
            v0.z = xs[(4 * q + 2) * SROW + p];
            v0.w = xs[(4 * q + 3) * SROW + p];
            v1.x = xs[(4 * q + 0) * SROW + 360 + p];
            v1.y = xs[(4 * q + 1) * SROW + 360 + p];
            v1.z = xs[(4 * q + 2) * SROW + 360 + p];
            v1.w = xs[(4 * q + 3) * SROW + 360 + p];
            *reinterpret_cast<float4*>(&g_xt0[b][p][ccol + 4 * q]) = v0;   // f0 scratch
            *reinterpret_cast<float4*>(
                out + obase + (size_t)(122 + p) * NC + ccol + 4 * q) = v1; // f1 final
        }

        __syncthreads();   // all stores ordered before the release below
        if (tid == 0)
            asm volatile("red.release.gpu.global.add.s32 [%0], 1;"
                         :: "l"(&g_cnt[b * 32]) : "memory");
    }
    else {
        // ================= sort path (dispatched last) =====================
        const int b = bid - BID_SORT;
        float* sv = sbuf;                                 // [512]
        int*   si = reinterpret_cast<int*>(sbuf + 512);   // [512]

        if (tid == 0) {
            int v;
            do {
                __nanosleep(64);
                asm volatile("ld.acquire.gpu.global.s32 %0, [%1];"
                             : "=r"(v) : "l"(&g_cnt[b * 32]) : "memory");
            } while (v < CSPLIT);
        }
        __syncthreads();   // acquire ordering propagates via barrier

        for (int e = tid; e < 512; e += 256) {
            float vsum = -CUDART_INF_F;
            if (e < NP) {
                float a0 = 0.f, a1 = 0.f, a2 = 0.f, a3 = 0.f;
                #pragma unroll
                for (int k = 0; k < CSPLIT; k += 4) {
                    a0 += g_spart[b][k + 0][e];
                    a1 += g_spart[b][k + 1][e];
                    a2 += g_spart[b][k + 2][e];
                    a3 += g_spart[b][k + 3][e];
                }
                vsum = (a0 + a1) + (a2 + a3);
            }
            sv[e] = vsum;
            si[e] = e;
        }
        __syncthreads();

        // bitonic sort 512 (desc score, asc idx tiebreak = lax.top_k semantics)
        for (int k = 2; k <= 512; k <<= 1) {
            for (int j = k >> 1; j > 0; j >>= 1) {
                const int l = 2 * tid - (tid & (j - 1));   // l & j == 0
                const int m = l | j;
                const float a = sv[l], c = sv[m];
                const int   ia = si[l], ic = si[m];
                const bool a_after = (a < c) || (a == c && ia > ic);
                const bool dir_desc = ((l & k) == 0);
                if (dir_desc ? a_after : !a_after) {
                    sv[l] = c; sv[m] = a; si[l] = ic; si[m] = ia;
                }
                __syncthreads();
            }
        }

        if (tid < NK) g_topk[b][tid] = si[tid];

        // cls rows: row 0 = cls[b,0,:], row 121 = cls[b,1,:]
        const size_t obase = (size_t)b * ROWS * NC;
        const float4* c4 = reinterpret_cast<const float4*>(cls + (size_t)b * NT * NC);
        float4* o4 = reinterpret_cast<float4*>(out + obase);
        for (int c = tid; c < NC / 4; c += 256) {
            o4[c]                = c4[c];               // row 0   (t=0 cls)
            o4[121 * (NC/4) + c] = c4[(NC/4) + c];      // row 121 (t=1 cls)
        }
    }
}

// ---------------------------------------------------------------------------
// Kernel C: dense gather of the 120 selected frame-0 rows from g_xt0 (L2-hot).
// grid (NK, NB), block 256: one 4 KB contiguous row copy per block.
// Block (0, b) also resets that b's counter for the next graph replay
// (g_cnt is only consumed in kernel A of the same replay, which has finished).
// ---------------------------------------------------------------------------
__global__ void __launch_bounds__(256) k_gather(float* __restrict__ out)
{
    const int rank = blockIdx.x;     // 0..119
    const int b    = blockIdx.y;     // 0..15
    const int tid  = threadIdx.x;

    if (rank == 0 && tid == 0)
        g_cnt[b * 32] = 0;           // reset for next replay

    const int p = g_topk[b][rank];
    const float4 v = *reinterpret_cast<const float4*>(&g_xt0[b][p][tid * 4]);
    *reinterpret_cast<float4*>(
        out + ((size_t)b * ROWS + 1 + rank) * NC + tid * 4) = v;
}

// ---------------------------------------------------------------------------
extern "C" void kernel_launch(void* const* d_in, const int* in_sizes, int n_in,
                              void* d_out, int out_size)
{
    const float* x   = (const float*)d_in[0];   // [16,1024,16,12,30]
    const float* cls = (const float*)d_in[1];   // [16,16,1024]
    float* out = (float*)d_out;                 // [16,482,1024]

    k_phase1<<<GRID_A, 256>>>(x, cls, out);
    k_gather<<<dim3(NK, NB), 256>>>(out);
}

// round 12
// speedup vs baseline: 1.0909x; 1.0909x over previous
#include <cuda_runtime.h>
#include <cuda_bf16.h>
#include <math_constants.h>
#include <cstdint>

// Problem constants
#define NB   16
#define NC   1024
#define NT   16
#define NP   360          // H*W = 12*30
#define NK   120          // top-k
#define ROWS 482          // 1 + 120 + 1 + 360
#define NSLICE 128                   // partial-score slices (8 c each)
#define TSTRIDE ((size_t)NT * NP)    // 5760 floats between consecutive c

// Phase-1 block roles (bid order: producers before consumers -> no deadlock)
#define N_SCORE 1024                 // 16 b x 64 cs (16 c per block)
#define N_COPY1 1536                 // 32 ct x 3 pt x 16 b
#define BID_COPY1 N_SCORE
#define BID_SORT  (N_SCORE + N_COPY1)
#define GRID_P1   (BID_SORT + NB)

// Scratch (no device allocation allowed -> __device__ globals)
__device__ __align__(16) float g_spart[NB][NSLICE][NP];   // 2.95 MB
__device__ int g_posmap[NB][NP];
__device__ int g_cnt[NB * 32];   // per-b score-block counters (128B padded), init 0

// evict_last load via cache-policy (bare .L2::evict_last on ld.v4.f32 is
// rejected by ptxas on sm_103; the createpolicy + cache_hint form is legal).
__device__ __forceinline__ float4 ld_evict_last(const float* p, uint64_t pol)
{
    float4 v;
    asm volatile("ld.global.nc.L2::cache_hint.v4.f32 {%0,%1,%2,%3}, [%4], %5;"
                 : "=f"(v.x), "=f"(v.y), "=f"(v.z), "=f"(v.w)
                 : "l"(p), "l"(pol));
    return v;
}

// ---------------------------------------------------------------------------
// Phase 1: scores (LDG + evict_last policy, pins f0 in L2) | frame-1 copy
// (evict-first streaming) | per-b sort (dispatched last, acquire-spin).
// ---------------------------------------------------------------------------
__global__ void __launch_bounds__(256, 3) k_phase1(const float* __restrict__ x,
                                                   const float* __restrict__ cls,
                                                   float* __restrict__ out)
{
    __shared__ __align__(16) float sbuf[4 * 1057 + 32];   // 17 KB, role-aliased
    const int bid = blockIdx.x;
    const int tid = threadIdx.x;

    if (bid < N_SCORE) {
        // ============ score path: 16 c x 360 p partial dots ================
        const int b  = bid >> 6;          // 0..15
        const int cs = bid & 63;          // 0..63
        if (tid < 180) {
            uint64_t pol;
            asm volatile("createpolicy.fractional.L2::evict_last.b64 %0, 1.0;"
                         : "=l"(pol));

            const int half  = tid / 90;          // 0..1 -> 8-c slice
            const int pq    = tid - half * 90;   // 0..89 p-quad
            const int cbase = cs * 16 + half * 8;

            const float* wp = cls + b * (NT * NC) + cbase;     // t=0 cls
            const float* xb = x + ((size_t)b * NC + cbase) * TSTRIDE + pq * 4;

            float4 v[8];
            float  w[8];
            #pragma unroll
            for (int j = 0; j < 8; ++j)
                v[j] = ld_evict_last(xb + (size_t)j * TSTRIDE, pol);
            #pragma unroll
            for (int j = 0; j < 8; ++j)
                w[j] = __ldg(wp + j);

            float4 acc = make_float4(0.f, 0.f, 0.f, 0.f);
            #pragma unroll
            for (int j = 0; j < 8; ++j) {
                acc.x = fmaf(w[j], v[j].x, acc.x);
                acc.y = fmaf(w[j], v[j].y, acc.y);
                acc.z = fmaf(w[j], v[j].z, acc.z);
                acc.w = fmaf(w[j], v[j].w, acc.w);
            }
            *reinterpret_cast<float4*>(&g_spart[b][cs * 2 + half][pq * 4]) = acc;
        }
        __syncthreads();   // partials ordered before release
        if (tid == 0)
            asm volatile("red.release.gpu.global.add.s32 [%0], 1;"
                         :: "l"(&g_cnt[b * 32]) : "memory");
    }
    else if (bid < BID_SORT) {
        // ============ frame-1 transpose copy (streaming, evict-first) ======
        const int idx = bid - BID_COPY1;     // 0..1535
        const int ct  = idx & 31;            // c tile of 32
        const int rem = idx >> 5;
        const int pt  = rem % 3;             // p tile of 128
        const int b   = rem / 3;             // 0..15

        float* tiles = sbuf;                 // [4][1057], stride 1057 == 1 (mod 32)
        const float* xbase = x + ((size_t)b * NC + ct * 32) * TSTRIDE + NP; // t=1
        const int pbase = pt * 128;

        #pragma unroll
        for (int i = 0; i < 4; ++i) {
            const int s  = tid + 256 * i;
            const int cl = s >> 5;           // 0..31
            const int pq = s & 31;           // 0..31
            const int p  = pbase + pq * 4;
            if (p < NP) {
                const float4 v = __ldcs(reinterpret_cast<const float4*>(
                    xbase + (size_t)cl * TSTRIDE + p));
                const int sidx = cl * 33 + pq;
                tiles[0 * 1057 + sidx] = v.x;
                tiles[1 * 1057 + sidx] = v.y;
                tiles[2 * 1057 + sidx] = v.z;
                tiles[3 * 1057 + sidx] = v.w;
            }
        }
        __syncthreads();

        const size_t obase = (size_t)b * ROWS * NC;
        #pragma unroll
        for (int i = 0; i < 4; ++i) {
            const int s  = tid + 256 * i;
            const int cq = s & 7;            // 0..7
            const int pl = s >> 3;           // 0..127
            const int pg = pbase + pl;
            if (pg < NP) {
                const int row = 122 + pg;
                const int j  = pl & 3;
                const int pq = pl >> 2;
                float4 w;
                w.x = tiles[j * 1057 + (4 * cq + 0) * 33 + pq];
                w.y = tiles[j * 1057 + (4 * cq + 1) * 33 + pq];
                w.z = tiles[j * 1057 + (4 * cq + 2) * 33 + pq];
                w.w = tiles[j * 1057 + (4 * cq + 3) * 33 + pq];
                __stcs(reinterpret_cast<float4*>(
                    out + obase + (size_t)row * NC + ct * 32 + cq * 4), w);
            }
        }
    }
    else {
        // ============ sort path (dispatched last) ==========================
        const int b = bid - BID_SORT;
        float* sv = sbuf;                                 // [512]
        int*   si = reinterpret_cast<int*>(sbuf + 512);   // [512]

        if (tid == 0) {
            int v;
            do {
                __nanosleep(64);
                asm volatile("ld.acquire.gpu.global.s32 %0, [%1];"
                             : "=r"(v) : "l"(&g_cnt[b * 32]) : "memory");
            } while (v < 64);   // 64 score blocks per b
        }
        __syncthreads();   // acquire ordering propagates via barrier

        for (int e = tid; e < 512; e += 256) {
            float vsum = -CUDART_INF_F;
            if (e < NP) {
                float a0 = 0.f, a1 = 0.f, a2 = 0.f, a3 = 0.f;
                #pragma unroll 8
                for (int k = 0; k < NSLICE; k += 4) {
                    a0 += g_spart[b][k + 0][e];
                    a1 += g_spart[b][k + 1][e];
                    a2 += g_spart[b][k + 2][e];
                    a3 += g_spart[b][k + 3][e];
                }
                vsum = (a0 + a1) + (a2 + a3);
            }
            sv[e] = vsum;
            si[e] = e;
        }
        __syncthreads();

        // bitonic sort 512 (desc score, asc idx tiebreak = lax.top_k semantics)
        for (int k = 2; k <= 512; k <<= 1) {
            for (int j = k >> 1; j > 0; j >>= 1) {
                const int l = 2 * tid - (tid & (j - 1));   // l & j == 0
                const int m = l | j;
                const float a = sv[l], c = sv[m];
                const int   ia = si[l], ic = si[m];
                const bool a_after = (a < c) || (a == c && ia > ic);
                const bool dir_desc = ((l & k) == 0);
                if (dir_desc ? a_after : !a_after) {
                    sv[l] = c; sv[m] = a; si[l] = ic; si[m] = ia;
                }
                __syncthreads();
            }
        }

        for (int p = tid; p < NP; p += 256) g_posmap[b][p] = -1;
        __syncthreads();
        if (tid < NK) g_posmap[b][si[tid]] = 1 + tid;

        // cls rows: row 0 = cls[b,0,:], row 121 = cls[b,1,:]
        const size_t obase = (size_t)b * ROWS * NC;
        const float4* c4 = reinterpret_cast<const float4*>(cls + (size_t)b * NT * NC);
        float4* o4 = reinterpret_cast<float4*>(out + obase);
        for (int c = tid; c < NC / 4; c += 256) {
            o4[c]                = c4[c];               // row 0   (t=0 cls)
            o4[121 * (NC/4) + c] = c4[(NC/4) + c];      // row 121 (t=1 cls)
        }
    }
}

// ---------------------------------------------------------------------------
// Phase 2: frame-0 selective transpose copy. f0 was loaded with evict_last
// policy in phase 1, so these reads should be L2 hits. Block (0,0,0) resets
// the counters for the next graph replay.
// ---------------------------------------------------------------------------
__global__ void __launch_bounds__(256) k_copy0(const float* __restrict__ x,
                                               float* __restrict__ out)
{
    const int ct = blockIdx.x;          // 0..31
    const int pt = blockIdx.y;          // 0..2
    const int b  = blockIdx.z;
    const int tid = threadIdx.x;

    if (ct == 0 && pt == 0 && b == 0 && tid < NB)
        g_cnt[tid * 32] = 0;            // reset for next replay

    __shared__ float tiles[4][1057];

    const float* xbase = x + ((size_t)b * NC + ct * 32) * TSTRIDE;  // t=0
    const int pbase = pt * 128;

    #pragma unroll
    for (int i = 0; i < 4; ++i) {
        const int s  = tid + 256 * i;
        const int cl = s >> 5;
        const int pq = s & 31;
        const int p  = pbase + pq * 4;
        if (p < NP) {
            const float4 v = __ldcs(reinterpret_cast<const float4*>(
                xbase + (size_t)cl * TSTRIDE + p));
            const int idx = cl * 33 + pq;
            tiles[0][idx] = v.x;
            tiles[1][idx] = v.y;
            tiles[2][idx] = v.z;
            tiles[3][idx] = v.w;
        }
    }
    __syncthreads();

    const size_t obase = (size_t)b * ROWS * NC;
    #pragma unroll
    for (int i = 0; i < 4; ++i) {
        const int s  = tid + 256 * i;
        const int cq = s & 7;
        const int pl = s >> 3;
        const int pg = pbase + pl;
        if (pg < NP) {
            const int row = g_posmap[b][pg];
            if (row >= 0) {
                const int j  = pl & 3;
                const int pq = pl >> 2;
                float4 w;
                w.x = tiles[j][(4 * cq + 0) * 33 + pq];
                w.y = tiles[j][(4 * cq + 1) * 33 + pq];
                w.z = tiles[j][(4 * cq + 2) * 33 + pq];
                w.w = tiles[j][(4 * cq + 3) * 33 + pq];
                *reinterpret_cast<float4*>(
                    out + obase + (size_t)row * NC + ct * 32 + cq * 4) = w;
            }
        }
    }
}

// ---------------------------------------------------------------------------
extern "C" void kernel_launch(void* const* d_in, const int* in_sizes, int n_in,
                              void* d_out, int out_size)
{
    const float* x   = (const float*)d_in[0];   // [16,1024,16,12,30]
    const float* cls = (const float*)d_in[1];   // [16,16,1024]
    float* out = (float*)d_out;                 // [16,482,1024]

    k_phase1<<<GRID_P1, 256>>>(x, cls, out);
    k_copy0<<<dim3(32, 3, NB), 256>>>(x, out);
}

// round 13
// speedup vs baseline: 1.1462x; 1.0507x over previous
#include <cuda_runtime.h>
#include <cuda_bf16.h>
#include <math_constants.h>
#include <cstdint>

// Problem constants
#define NB   16
#define NC   1024
#define NT   16
#define NP   360          // H*W = 12*30
#define NK   120          // top-k
#define ROWS 482          // 1 + 120 + 1 + 360
#define NSLICE 128                   // partial-score slices (8 c each)
#define TSTRIDE ((size_t)NT * NP)    // 5760 floats between consecutive c

// Phase-1 block roles (bid order: producers before consumers -> no deadlock)
#define N_SCORE 1024                 // 16 b x 64 cs (16 c per block)
#define N_COPY1 1536                 // 32 ct x 3 pt x 16 b
#define BID_COPY1 N_SCORE
#define BID_SORT  (N_SCORE + N_COPY1)
#define GRID_P1   (BID_SORT + NB)

// Scratch (no device allocation allowed -> __device__ globals)
__device__ __align__(16) float g_spart[NB][NSLICE][NP];   // 2.95 MB
__device__ int g_posmap[NB][NP];
__device__ int g_cnt[NB * 32];   // per-b score-block counters (128B padded), init 0

// ---------------------------------------------------------------------------
// Phase 1: scores (plain LDG — proven to leave f0 L2-resident for phase 2)
//        | frame-1 transpose copy (plain, R5-identical)
//        | per-b sort (dispatched last, release/acquire counter sync).
// ---------------------------------------------------------------------------
__global__ void __launch_bounds__(256, 3) k_phase1(const float* __restrict__ x,
                                                   const float* __restrict__ cls,
                                                   float* __restrict__ out)
{
    __shared__ __align__(16) float sbuf[4 * 1057 + 32];   // 17 KB, role-aliased
    const int bid = blockIdx.x;
    const int tid = threadIdx.x;

    if (bid < N_SCORE) {
        // ============ score path: 16 c x 360 p partial dots ================
        const int b  = bid >> 6;          // 0..15
        const int cs = bid & 63;          // 0..63
        if (tid < 180) {
            const int half  = tid / 90;          // 0..1 -> 8-c slice
            const int pq    = tid - half * 90;   // 0..89 p-quad
            const int cbase = cs * 16 + half * 8;

            const float* wp = cls + b * (NT * NC) + cbase;     // t=0 cls
            const float* xb = x + ((size_t)b * NC + cbase) * TSTRIDE + pq * 4;

            float4 v[8];
            float  w[8];
            #pragma unroll
            for (int j = 0; j < 8; ++j)
                v[j] = *reinterpret_cast<const float4*>(xb + (size_t)j * TSTRIDE);
            #pragma unroll
            for (int j = 0; j < 8; ++j)
                w[j] = __ldg(wp + j);

            float4 acc = make_float4(0.f, 0.f, 0.f, 0.f);
            #pragma unroll
            for (int j = 0; j < 8; ++j) {
                acc.x = fmaf(w[j], v[j].x, acc.x);
                acc.y = fmaf(w[j], v[j].y, acc.y);
                acc.z = fmaf(w[j], v[j].z, acc.z);
                acc.w = fmaf(w[j], v[j].w, acc.w);
            }
            *reinterpret_cast<float4*>(&g_spart[b][cs * 2 + half][pq * 4]) = acc;
        }
        __syncthreads();   // partials ordered before release
        if (tid == 0)
            asm volatile("red.release.gpu.global.add.s32 [%0], 1;"
                         :: "l"(&g_cnt[b * 32]) : "memory");
    }
    else if (bid < BID_SORT) {
        // ============ frame-1 transpose copy (independent, R5 k_mid) =======
        const int idx = bid - BID_COPY1;     // 0..1535
        const int ct  = idx & 31;            // c tile of 32
        const int rem = idx >> 5;
        const int pt  = rem % 3;             // p tile of 128
        const int b   = rem / 3;             // 0..15

        float* tiles = sbuf;                 // [4][1057], stride 1057 == 1 (mod 32)
        const float* xbase = x + ((size_t)b * NC + ct * 32) * TSTRIDE + NP; // t=1
        const int pbase = pt * 128;

        #pragma unroll
        for (int i = 0; i < 4; ++i) {
            const int s  = tid + 256 * i;
            const int cl = s >> 5;           // 0..31
            const int pq = s & 31;           // 0..31
            const int p  = pbase + pq * 4;
            if (p < NP) {
                const float4 v = *reinterpret_cast<const float4*>(
                    xbase + (size_t)cl * TSTRIDE + p);
                const int sidx = cl * 33 + pq;
                tiles[0 * 1057 + sidx] = v.x;
                tiles[1 * 1057 + sidx] = v.y;
                tiles[2 * 1057 + sidx] = v.z;
                tiles[3 * 1057 + sidx] = v.w;
            }
        }
        __syncthreads();

        const size_t obase = (size_t)b * ROWS * NC;
        #pragma unroll
        for (int i = 0; i < 4; ++i) {
            const int s  = tid + 256 * i;
            const int cq = s & 7;            // 0..7
            const int pl = s >> 3;           // 0..127
            const int pg = pbase + pl;
            if (pg < NP) {
                const int row = 122 + pg;
                const int j  = pl & 3;
                const int pq = pl >> 2;
                float4 w;
                w.x = tiles[j * 1057 + (4 * cq + 0) * 33 + pq];
                w.y = tiles[j * 1057 + (4 * cq + 1) * 33 + pq];
                w.z = tiles[j * 1057 + (4 * cq + 2) * 33 + pq];
                w.w = tiles[j * 1057 + (4 * cq + 3) * 33 + pq];
                *reinterpret_cast<float4*>(
                    out + obase + (size_t)row * NC + ct * 32 + cq * 4) = w;
            }
        }
    }
    else {
        // ============ sort path (dispatched last) ==========================
        const int b = bid - BID_SORT;
        float* sv = sbuf;                                 // [512]
        int*   si = reinterpret_cast<int*>(sbuf + 512);   // [512]

        if (tid == 0) {
            int v;
            do {
                __nanosleep(64);
                asm volatile("ld.acquire.gpu.global.s32 %0, [%1];"
                             : "=r"(v) : "l"(&g_cnt[b * 32]) : "memory");
            } while (v < 64);   // 64 score blocks per b
        }
        __syncthreads();   // acquire ordering propagates via barrier

        for (int e = tid; e < 512; e += 256) {
            float vsum = -CUDART_INF_F;
            if (e < NP) {
                float a0 = 0.f, a1 = 0.f, a2 = 0.f, a3 = 0.f;
                #pragma unroll 8
                for (int k = 0; k < NSLICE; k += 4) {
                    a0 += g_spart[b][k + 0][e];
                    a1 += g_spart[b][k + 1][e];
                    a2 += g_spart[b][k + 2][e];
                    a3 += g_spart[b][k + 3][e];
                }
                vsum = (a0 + a1) + (a2 + a3);
            }
            sv[e] = vsum;
            si[e] = e;
        }
        __syncthreads();

        // bitonic sort 512 (desc score, asc idx tiebreak = lax.top_k semantics)
        for (int k = 2; k <= 512; k <<= 1) {
            for (int j = k >> 1; j > 0; j >>= 1) {
                const int l = 2 * tid - (tid & (j - 1));   // l & j == 0
                const int m = l | j;
                const float a = sv[l], c = sv[m];
                const int   ia = si[l], ic = si[m];
                const bool a_after = (a < c) || (a == c && ia > ic);
                const bool dir_desc = ((l & k) == 0);
                if (dir_desc ? a_after : !a_after) {
                    sv[l] = c; sv[m] = a; si[l] = ic; si[m] = ia;
                }
                __syncthreads();
            }
        }

        for (int p = tid; p < NP; p += 256) g_posmap[b][p] = -1;
        __syncthreads();
        if (tid < NK) g_posmap[b][si[tid]] = 1 + tid;

        // cls rows: row 0 = cls[b,0,:], row 121 = cls[b,1,:]
        const size_t obase = (size_t)b * ROWS * NC;
        const float4* c4 = reinterpret_cast<const float4*>(cls + (size_t)b * NT * NC);
        float4* o4 = reinterpret_cast<float4*>(out + obase);
        for (int c = tid; c < NC / 4; c += 256) {
            o4[c]                = c4[c];               // row 0   (t=0 cls)
            o4[121 * (NC/4) + c] = c4[(NC/4) + c];      // row 121 (t=1 cls)
        }
    }
}

// ---------------------------------------------------------------------------
// Phase 2: frame-0 selective transpose copy (R5-identical, plain loads; f0 is
// L2-resident from the plain-LDG score pass). Block (0,0,0) resets counters
// for the next graph replay.
// ---------------------------------------------------------------------------
__global__ void __launch_bounds__(256) k_copy0(const float* __restrict__ x,
                                               float* __restrict__ out)
{
    const int ct = blockIdx.x;          // 0..31
    const int pt = blockIdx.y;          // 0..2
    const int b  = blockIdx.z;
    const int tid = threadIdx.x;

    if (ct == 0 && pt == 0 && b == 0 && tid < NB)
        g_cnt[tid * 32] = 0;            // reset for next replay

    __shared__ float tiles[4][1057];

    const float* xbase = x + ((size_t)b * NC + ct * 32) * TSTRIDE;  // t=0
    const int pbase = pt * 128;

    #pragma unroll
    for (int i = 0; i < 4; ++i) {
        const int s  = tid + 256 * i;
        const int cl = s >> 5;
        const int pq = s & 31;
        const int p  = pbase + pq * 4;
        if (p < NP) {
            const float4 v = *reinterpret_cast<const float4*>(
                xbase + (size_t)cl * TSTRIDE + p);
            const int idx = cl * 33 + pq;
            tiles[0][idx] = v.x;
            tiles[1][idx] = v.y;
            tiles[2][idx] = v.z;
            tiles[3][idx] = v.w;
        }
    }
    __syncthreads();

    const size_t obase = (size_t)b * ROWS * NC;
    #pragma unroll
    for (int i = 0; i < 4; ++i) {
        const int s  = tid + 256 * i;
        const int cq = s & 7;
        const int pl = s >> 3;
        const int pg = pbase + pl;
        if (pg < NP) {
            const int row = g_posmap[b][pg];
            if (row >= 0) {
                const int j  = pl & 3;
                const int pq = pl >> 2;
                float4 w;
                w.x = tiles[j][(4 * cq + 0) * 33 + pq];
                w.y = tiles[j][(4 * cq + 1) * 33 + pq];
                w.z = tiles[j][(4 * cq + 2) * 33 + pq];
                w.w = tiles[j][(4 * cq + 3) * 33 + pq];
                *reinterpret_cast<float4*>(
                    out + obase + (size_t)row * NC + ct * 32 + cq * 4) = w;
            }
        }
    }
}

// ---------------------------------------------------------------------------
extern "C" void kernel_launch(void* const* d_in, const int* in_sizes, int n_in,
                              void* d_out, int out_size)
{
    const float* x   = (const float*)d_in[0];   // [16,1024,16,12,30]
    const float* cls = (const float*)d_in[1];   // [16,16,1024]
    float* out = (float*)d_out;                 // [16,482,1024]

    k_phase1<<<GRID_P1, 256>>>(x, cls, out);
    k_copy0<<<dim3(32, 3, NB), 256>>>(x, out);
}

// round 14
// speedup vs baseline: 1.2351x; 1.0775x over previous
#include <cuda_runtime.h>
#include <cuda_bf16.h>
#include <math_constants.h>
#include <cstdint>

// Problem constants
#define NB   16
#define NC   1024
#define NT   16
#define NP   360          // H*W = 12*30
#define NK   120          // top-k
#define ROWS 482          // 1 + 120 + 1 + 360
#define TSTRIDE ((size_t)NT * NP)   // 5760 floats between consecutive c

// Kernel-A roles: 1536 tile blocks (32ct x 3pt x 16b), then 16 sort blocks
#define N_TILE  1536
#define GRID_A  (N_TILE + NB)

// Scratch (no device allocation allowed -> __device__ globals)
__device__ __align__(16) float g_xt0[NB][NP][NC];        // 23.6 MB f0 transposed
__device__ __align__(16) float g_spart[NB][32][NP];      // 737 KB partial scores
__device__ int g_topk[NB][128];
__device__ int g_cnt[NB * 32];   // per-b tile-block counters (128B padded), init 0

// ---------------------------------------------------------------------------
// Kernel A — single pass over x.
// Tile block (b, ct, pt):
//   1) load f0 tile (32c x 128p) into conflict-free component-split smem
//   2) transposed store to g_xt0[b][p][ct*32..+32) (128B full-line segments)
//      + in the same loop, dot each c-quad with cls -> part[pl][cq]
//   3) reduce part rows -> g_spart[b][ct][p]; release per-b counter
//   4) load f1 tile, transposed store to out rows 122+p (final)
// Sort block (b), dispatched last: spin until counter==96, reduce 32 partials,
//   bitonic sort 512 (desc score, asc idx tiebreak = lax.top_k), emit
//   g_topk + both cls rows.
// ---------------------------------------------------------------------------
__global__ void __launch_bounds__(256) k_main(const float* __restrict__ x,
                                              const float* __restrict__ cls,
                                              float* __restrict__ out)
{
    // role-aliased smem: tiles [4][1057] | part [128][9] | cls_s [32]
    __shared__ __align__(16) float sbuf[4 * 1057 + 128 * 9 + 32];
    const int bid = blockIdx.x;
    const int tid = threadIdx.x;

    if (bid < N_TILE) {
        const int ct  = bid & 31;            // c tile of 32
        const int rem = bid >> 5;
        const int pt  = rem % 3;             // p tile of 128
        const int b   = rem / 3;             // 0..15

        float* tiles = sbuf;                 // stride 1057 == 1 (mod 32)
        float* part  = sbuf + 4 * 1057;      // [128][9]
        float* cls_s = part + 128 * 9;       // [32]

        const int pbase = pt * 128;
        const size_t xoff = ((size_t)b * NC + ct * 32) * TSTRIDE;

        if (tid < 32)
            cls_s[tid] = cls[b * (NT * NC) + ct * 32 + tid];   // t=0 cls

        // ---- 1) load f0 tile ----
        {
            const float* xbase = x + xoff;   // t=0
            #pragma unroll
            for (int i = 0; i < 4; ++i) {
                const int s  = tid + 256 * i;
                const int cl = s >> 5;       // 0..31
                const int pq = s & 31;       // 0..31
                const int p  = pbase + pq * 4;
                if (p < NP) {
                    const float4 v = *reinterpret_cast<const float4*>(
                        xbase + (size_t)cl * TSTRIDE + p);
                    const int sidx = cl * 33 + pq;
                    tiles[0 * 1057 + sidx] = v.x;
                    tiles[1 * 1057 + sidx] = v.y;
                    tiles[2 * 1057 + sidx] = v.z;
                    tiles[3 * 1057 + sidx] = v.w;
                }
            }
        }
        __syncthreads();

        // ---- 2) transposed store to xt0 + per-(pl,cq) dots ----
        #pragma unroll
        for (int i = 0; i < 4; ++i) {
            const int s  = tid + 256 * i;
            const int cq = s & 7;            // 0..7
            const int pl = s >> 3;           // 0..127
            const int pg = pbase + pl;
            if (pg < NP) {
                const int j  = pl & 3;
                const int pq = pl >> 2;
                float4 w;
                w.x = tiles[j * 1057 + (4 * cq + 0) * 33 + pq];
                w.y = tiles[j * 1057 + (4 * cq + 1) * 33 + pq];
                w.z = tiles[j * 1057 + (4 * cq + 2) * 33 + pq];
                w.w = tiles[j * 1057 + (4 * cq + 3) * 33 + pq];
                *reinterpret_cast<float4*>(&g_xt0[b][pg][ct * 32 + cq * 4]) = w;
                // score contribution of this c-quad (fixed order -> deterministic)
                const float d = fmaf(cls_s[4 * cq + 0], w.x,
                                fmaf(cls_s[4 * cq + 1], w.y,
                                fmaf(cls_s[4 * cq + 2], w.z,
                                     cls_s[4 * cq + 3] * w.w)));
                part[pl * 9 + cq] = d;
            }
        }
        __syncthreads();

        // ---- 3) reduce 8 c-quads per p, release ----
        if (tid < 128) {
            const int pg = pbase + tid;
            if (pg < NP) {
                const float* pr = &part[tid * 9];
                const float sum = ((pr[0] + pr[1]) + (pr[2] + pr[3]))
                                + ((pr[4] + pr[5]) + (pr[6] + pr[7]));
                g_spart[b][ct][pg] = sum;
            }
        }
        __syncthreads();
        if (tid == 0)
            asm volatile("red.release.gpu.global.add.s32 [%0], 1;"
                         :: "l"(&g_cnt[b * 32]) : "memory");

        // ---- 4) f1 tile -> out rows 122..481 ----
        {
            const float* xbase = x + xoff + NP;   // t=1
            #pragma unroll
            for (int i = 0; i < 4; ++i) {
                const int s  = tid + 256 * i;
                const int cl = s >> 5;
                const int pq = s & 31;
                const int p  = pbase + pq * 4;
                if (p < NP) {
                    const float4 v = *reinterpret_cast<const float4*>(
                        xbase + (size_t)cl * TSTRIDE + p);
                    const int sidx = cl * 33 + pq;
                    tiles[0 * 1057 + sidx] = v.x;
                    tiles[1 * 1057 + sidx] = v.y;
                    tiles[2 * 1057 + sidx] = v.z;
                    tiles[3 * 1057 + sidx] = v.w;
                }
            }
        }
        __syncthreads();

        const size_t obase = (size_t)b * ROWS * NC;
        #pragma unroll
        for (int i = 0; i < 4; ++i) {
            const int s  = tid + 256 * i;
            const int cq = s & 7;
            const int pl = s >> 3;
            const int pg = pbase + pl;
            if (pg < NP) {
                const int row = 122 + pg;
                const int j  = pl & 3;
                const int pq = pl >> 2;
                float4 w;
                w.x = tiles[j * 1057 + (4 * cq + 0) * 33 + pq];
                w.y = tiles[j * 1057 + (4 * cq + 1) * 33 + pq];
                w.z = tiles[j * 1057 + (4 * cq + 2) * 33 + pq];
                w.w = tiles[j * 1057 + (4 * cq + 3) * 33 + pq];
                *reinterpret_cast<float4*>(
                    out + obase + (size_t)row * NC + ct * 32 + cq * 4) = w;
            }
        }
    }
    else {
        // ================= sort path (dispatched last) =====================
        const int b = bid - N_TILE;
        float* sv = sbuf;                                 // [512]
        int*   si = reinterpret_cast<int*>(sbuf + 512);   // [512]

        if (tid == 0) {
            int v;
            do {
                __nanosleep(64);
                asm volatile("ld.acquire.gpu.global.s32 %0, [%1];"
                             : "=r"(v) : "l"(&g_cnt[b * 32]) : "memory");
            } while (v < 96);   // 96 tile blocks per b (32ct x 3pt)
        }
        __syncthreads();   // acquire ordering propagates via barrier

        for (int e = tid; e < 512; e += 256) {
            float vsum = -CUDART_INF_F;
            if (e < NP) {
                float a0 = 0.f, a1 = 0.f, a2 = 0.f, a3 = 0.f;
                #pragma unroll
                for (int k = 0; k < 32; k += 4) {
                    a0 += g_spart[b][k + 0][e];
                    a1 += g_spart[b][k + 1][e];
                    a2 += g_spart[b][k + 2][e];
                    a3 += g_spart[b][k + 3][e];
                }
                vsum = (a0 + a1) + (a2 + a3);
            }
            sv[e] = vsum;
            si[e] = e;
        }
        __syncthreads();

        // bitonic sort 512 (desc score, asc idx tiebreak = lax.top_k semantics)
        for (int k = 2; k <= 512; k <<= 1) {
            for (int j = k >> 1; j > 0; j >>= 1) {
                const int l = 2 * tid - (tid & (j - 1));   // l & j == 0
                const int m = l | j;
                const float a = sv[l], c = sv[m];
                const int   ia = si[l], ic = si[m];
                const bool a_after = (a < c) || (a == c && ia > ic);
                const bool dir_desc = ((l & k) == 0);
                if (dir_desc ? a_after : !a_after) {
                    sv[l] = c; sv[m] = a; si[l] = ic; si[m] = ia;
                }
                __syncthreads();
            }
        }

        if (tid < NK) g_topk[b][tid] = si[tid];

        // cls rows: row 0 = cls[b,0,:], row 121 = cls[b,1,:]
        const size_t obase = (size_t)b * ROWS * NC;
        const float4* c4 = reinterpret_cast<const float4*>(cls + (size_t)b * NT * NC);
        float4* o4 = reinterpret_cast<float4*>(out + obase);
        for (int c = tid; c < NC / 4; c += 256) {
            o4[c]                = c4[c];               // row 0   (t=0 cls)
            o4[121 * (NC/4) + c] = c4[(NC/4) + c];      // row 121 (t=1 cls)
        }
    }
}

// ---------------------------------------------------------------------------
// Kernel B — gather the 120 selected frame-0 rows from g_xt0 (dense 4 KB rows,
// freshly written in kernel A so L2-hot). Block (0, b) resets that b's counter
// for the next graph replay.
// ---------------------------------------------------------------------------
__global__ void __launch_bounds__(256) k_gather(float* __restrict__ out)
{
    const int rank = blockIdx.x;     // 0..119
    const int b    = blockIdx.y;     // 0..15
    const int tid  = threadIdx.x;

    if (rank == 0 && tid == 0)
        g_cnt[b * 32] = 0;           // reset for next replay

    const int p = g_topk[b][rank];
    const float4 v = *reinterpret_cast<const float4*>(&g_xt0[b][p][tid * 4]);
    *reinterpret_cast<float4*>(
        out + ((size_t)b * ROWS + 1 + rank) * NC + tid * 4) = v;
}

// ---------------------------------------------------------------------------
extern "C" void kernel_launch(void* const* d_in, const int* in_sizes, int n_in,
                              void* d_out, int out_size)
{
    const float* x   = (const float*)d_in[0];   // [16,1024,16,12,30]
    const float* cls = (const float*)d_in[1];   // [16,16,1024]
    float* out = (float*)d_out;                 // [16,482,1024]

    k_main<<<GRID_A, 256>>>(x, cls, out);
    k_gather<<<dim3(NK, NB), 256>>>(out);
}